// round 14
// baseline (speedup 1.0000x reference)
#include <cuda_runtime.h>
#include <cuda_fp16.h>
#include <math.h>

#define NN 100000
#define NE 1600000
#define F0 500
#define F1 128
#define F2 64
#define F3 40
#define SCAN_B 1024
#define NBLK ((NN + SCAN_B - 1) / SCAN_B)

// Static scratch (allocation-free rule: __device__ globals)
__device__ int   g_cnt [NN];
__device__ int   g_off [NN];
__device__ int   g_cur [NN];
__device__ int   g_bsum[SCAN_B];
__device__ int   g_csr [NE];
__device__ float g_dinv[NN];
__device__ __align__(16) __half g_h [(size_t)NN * F1];   // GEMM outputs (fp16, scaled)
__device__ __align__(16) __half g_h2[(size_t)NN * F1];   // pull outputs (fp16)

// ---------------- degree / CSR build ----------------
__global__ void cnt_count_k(const int* __restrict__ dst, int e) {
    int i = blockIdx.x * blockDim.x + threadIdx.x;
    if (i < e) atomicAdd(&g_cnt[dst[i]], 1);
}
__global__ void dinv_k(int n) {
    int i = blockIdx.x * blockDim.x + threadIdx.x;
    if (i < n) g_dinv[i] = rsqrtf((float)(g_cnt[i] + 1));
}
__global__ void scan1_k(int n) {
    __shared__ int sh[SCAN_B];
    int t = threadIdx.x, g = blockIdx.x * SCAN_B + t;
    int v = (g < n) ? g_cnt[g] : 0;
    sh[t] = v; __syncthreads();
#pragma unroll
    for (int o = 1; o < SCAN_B; o <<= 1) {
        int x = (t >= o) ? sh[t - o] : 0;
        __syncthreads();
        sh[t] += x;
        __syncthreads();
    }
    if (g < n) g_off[g] = sh[t] - v;
    if (t == SCAN_B - 1) g_bsum[blockIdx.x] = sh[t];
}
__global__ void scan2_k(int nb) {
    __shared__ int sh[SCAN_B];
    int t = threadIdx.x;
    int v = (t < nb) ? g_bsum[t] : 0;
    sh[t] = v; __syncthreads();
#pragma unroll
    for (int o = 1; o < SCAN_B; o <<= 1) {
        int x = (t >= o) ? sh[t - o] : 0;
        __syncthreads();
        sh[t] += x;
        __syncthreads();
    }
    if (t < nb) g_bsum[t] = sh[t] - v;
}
__global__ void scan3_k(int n) {
    int i = blockIdx.x * blockDim.x + threadIdx.x;
    if (i < n) {
        int o = g_off[i] + g_bsum[i / SCAN_B];
        g_off[i] = o;
        g_cur[i] = o;
    }
}
__global__ void csr_fill_k(const int* __restrict__ src, const int* __restrict__ dst, int e) {
    int i = blockIdx.x * blockDim.x + threadIdx.x;
    if (i < e) {
        int pos = atomicAdd(&g_cur[dst[i]], 1);
        g_csr[pos] = src[i];
    }
}

// ---------------- async-copy / mma helpers ----------------
template<typename T>
__device__ __forceinline__ void cp16(T* s, const T* g, bool pred) {
    unsigned sa = (unsigned)__cvta_generic_to_shared(s);
    int bytes = pred ? 16 : 0;
    asm volatile("cp.async.ca.shared.global [%0], [%1], 16, %2;"
                 :: "r"(sa), "l"(g), "r"(bytes));
}
#define CP_COMMIT() asm volatile("cp.async.commit_group;" ::: "memory")
#define CP_WAIT(N)  asm volatile("cp.async.wait_group %0;" :: "n"(N) : "memory")

__device__ __forceinline__ void mma_f16(float* d, const unsigned* a, const unsigned* b) {
    asm volatile(
        "mma.sync.aligned.m16n8k16.row.col.f32.f16.f16.f32 "
        "{%0,%1,%2,%3},{%4,%5,%6,%7},{%8,%9},{%0,%1,%2,%3};"
        : "+f"(d[0]), "+f"(d[1]), "+f"(d[2]), "+f"(d[3])
        : "r"(a[0]), "r"(a[1]), "r"(a[2]), "r"(a[3]), "r"(b[0]), "r"(b[1]));
}
__device__ __forceinline__ unsigned h2u(__half2 h) { return *(unsigned*)&h; }

// ---------------- fp16 MMA GEMM (proven R13 kernel, unchanged) ----------
template<int BN, typename TI>
__global__ void __launch_bounds__(256) gemm_f16_k(
        const TI* __restrict__ X, const float* __restrict__ W,
        __half* __restrict__ hs, int M, int Kreal) {
    constexpr int BM = 128, BK = 32;
    constexpr int XSTR = 40;
    constexpr int WSTR = 34;
    constexpr int NJ = BN / 16;
    constexpr int WITER = (BK / 2) * BN / 256;
    constexpr bool XF32 = (sizeof(TI) == 4);

    __shared__ __half Xs[2][BM][XSTR];
    __shared__ __half Wt[2][BN][WSTR];

    const int tid    = threadIdx.x;
    const int lane   = tid & 31;
    const int wid    = tid >> 5;
    const int warp_m = wid & 3;
    const int warp_n = wid >> 2;
    const int row0   = blockIdx.x * BM;
    const int lq     = lane >> 2;
    const int lr     = lane & 3;

    float acc[2][NJ][4];
#pragma unroll
    for (int i = 0; i < 2; i++)
#pragma unroll
        for (int j = 0; j < NJ; j++)
#pragma unroll
            for (int t = 0; t < 4; t++) acc[i][j][t] = 0.f;

    const int nchunk = (Kreal + BK - 1) / BK;

    unsigned xr[2][4];
    auto ldxr = [&](int k0) {
#pragma unroll
        for (int it = 0; it < 2; it++) {
            int idx = tid + it * 256;
            int r = idx >> 2, kv = idx & 3;
            int gr = row0 + r; if (gr >= M) gr = M - 1;
            int gk = k0 + kv * 8;
            const float* p = (const float*)X + (size_t)gr * Kreal + gk;
            float4 v0 = (gk + 4 <= Kreal) ? *(const float4*)p
                                          : make_float4(0.f, 0.f, 0.f, 0.f);
            float4 v1 = (gk + 8 <= Kreal) ? *(const float4*)(p + 4)
                                          : make_float4(0.f, 0.f, 0.f, 0.f);
            xr[it][0] = h2u(__floats2half2_rn(v0.x, v0.y));
            xr[it][1] = h2u(__floats2half2_rn(v0.z, v0.w));
            xr[it][2] = h2u(__floats2half2_rn(v1.x, v1.y));
            xr[it][3] = h2u(__floats2half2_rn(v1.z, v1.w));
        }
    };
    auto stx = [&](int s) {
#pragma unroll
        for (int it = 0; it < 2; it++) {
            int idx = tid + it * 256;
            int r = idx >> 2, kv = idx & 3;
            *(uint4*)&Xs[s][r][kv * 8] =
                make_uint4(xr[it][0], xr[it][1], xr[it][2], xr[it][3]);
        }
    };
    auto cpx = [&](int s, int k0) {
#pragma unroll
        for (int it = 0; it < 2; it++) {
            int idx = tid + it * 256;
            int r = idx >> 2, kv = idx & 3;
            int gr = row0 + r; if (gr >= M) gr = M - 1;
            cp16(&Xs[s][r][kv * 8],
                 (const __half*)X + (size_t)gr * Kreal + k0 + kv * 8, true);
        }
    };

    float wr[WITER][2];
    auto ldw = [&](int k0) {
#pragma unroll
        for (int it = 0; it < WITER; it++) {
            int idx = tid + it * 256;
            int n   = idx % BN;
            int kp  = idx / BN;
            int gk  = k0 + 2 * kp;
            wr[it][0] = (gk     < Kreal) ? W[(size_t)gk * BN + n]       : 0.f;
            wr[it][1] = (gk + 1 < Kreal) ? W[(size_t)(gk + 1) * BN + n] : 0.f;
        }
    };
    auto stw = [&](int s) {
#pragma unroll
        for (int it = 0; it < WITER; it++) {
            int idx = tid + it * 256;
            int n   = idx % BN;
            int kp  = idx / BN;
            *(__half2*)&Wt[s][n][2 * kp] = __floats2half2_rn(wr[it][0], wr[it][1]);
        }
    };

    if (XF32) { ldxr(0); stx(0); if (nchunk > 1) ldxr(BK); }
    else      { cpx(0, 0); CP_COMMIT(); }
    ldw(0); stw(0);
    if (nchunk > 1) ldw(BK);

    for (int kc = 0; kc < nchunk; kc++) {
        const int s = kc & 1;
        if (XF32) {
            if (kc + 1 < nchunk) stx(s ^ 1);
            if (kc + 2 < nchunk) ldxr((kc + 2) * BK);
        } else {
            if (kc + 1 < nchunk) { cpx(s ^ 1, (kc + 1) * BK); CP_COMMIT(); CP_WAIT(1); }
            else                 { CP_WAIT(0); }
        }
        if (kc + 1 < nchunk) stw(s ^ 1);
        if (kc + 2 < nchunk) ldw((kc + 2) * BK);
        __syncthreads();

#pragma unroll
        for (int ks = 0; ks < 2; ks++) {
            const int kb = ks * 16;
            unsigned a[2][4], b[NJ][2];
#pragma unroll
            for (int i = 0; i < 2; i++) {
                int r = warp_m * 32 + i * 16;
                a[i][0] = *(const unsigned*)&Xs[s][r + lq    ][kb + lr * 2    ];
                a[i][1] = *(const unsigned*)&Xs[s][r + lq + 8][kb + lr * 2    ];
                a[i][2] = *(const unsigned*)&Xs[s][r + lq    ][kb + lr * 2 + 8];
                a[i][3] = *(const unsigned*)&Xs[s][r + lq + 8][kb + lr * 2 + 8];
            }
#pragma unroll
            for (int j = 0; j < NJ; j++) {
                int n = warp_n * (BN / 2) + j * 8 + lq;
                b[j][0] = *(const unsigned*)&Wt[s][n][kb + lr * 2    ];
                b[j][1] = *(const unsigned*)&Wt[s][n][kb + lr * 2 + 8];
            }
#pragma unroll
            for (int i = 0; i < 2; i++)
#pragma unroll
                for (int j = 0; j < NJ; j++) mma_f16(acc[i][j], a[i], b[j]);
        }
        __syncthreads();
    }

#pragma unroll
    for (int i = 0; i < 2; i++) {
        int r_lo = row0 + warp_m * 32 + i * 16 + lq;
        int r_hi = r_lo + 8;
        float dv_lo = (r_lo < M) ? g_dinv[r_lo] : 0.f;
        float dv_hi = (r_hi < M) ? g_dinv[r_hi] : 0.f;
#pragma unroll
        for (int j = 0; j < NJ; j++) {
            int c = warp_n * (BN / 2) + j * 8 + lr * 2;
            if (r_lo < M)
                *(__half2*)&hs[(size_t)r_lo * BN + c] =
                    __floats2half2_rn(acc[i][j][0] * dv_lo, acc[i][j][1] * dv_lo);
            if (r_hi < M)
                *(__half2*)&hs[(size_t)r_hi * BN + c] =
                    __floats2half2_rn(acc[i][j][2] * dv_hi, acc[i][j][3] * dv_hi);
        }
    }
}

// ---------------- fp32 GEMM for 64->40, half in / half out ----------------
template<int BM, int BN, int BK, int TM, int TN>
__global__ void gemm_scale_k(const __half* __restrict__ X, const float* __restrict__ W,
                             __half* __restrict__ hs, int M, int K) {
    __shared__ float Xs[BM][BK + 1];
    __shared__ float Ws[BK][BN];
    constexpr int NT = (BM / TM) * (BN / TN);
    const int tid = threadIdx.x;
    const int tx  = tid % (BN / TN);
    const int ty  = tid / (BN / TN);
    const int row0 = blockIdx.x * BM;

    float acc[TM][TN];
#pragma unroll
    for (int i = 0; i < TM; i++)
#pragma unroll
        for (int j = 0; j < TN; j++) acc[i][j] = 0.f;

    for (int k0 = 0; k0 < K; k0 += BK) {
        for (int i = tid; i < BM * BK; i += NT) {
            int r = i / BK, kk = i % BK;
            int gr = row0 + r; if (gr >= M) gr = M - 1;
            int gk = k0 + kk;
            Xs[r][kk] = (gk < K) ? __half2float(X[(size_t)gr * K + gk]) : 0.f;
        }
        for (int i = tid; i < BK * BN; i += NT) {
            int kk = i / BN, c = i % BN;
            int gk = k0 + kk;
            Ws[kk][c] = (gk < K) ? W[(size_t)gk * BN + c] : 0.f;
        }
        __syncthreads();
#pragma unroll
        for (int kk = 0; kk < BK; kk++) {
            float a[TM], b[TN];
#pragma unroll
            for (int i = 0; i < TM; i++) a[i] = Xs[ty * TM + i][kk];
#pragma unroll
            for (int j = 0; j < TN; j++) b[j] = Ws[kk][tx * TN + j];
#pragma unroll
            for (int i = 0; i < TM; i++)
#pragma unroll
                for (int j = 0; j < TN; j++) acc[i][j] += a[i] * b[j];
        }
        __syncthreads();
    }

#pragma unroll
    for (int i = 0; i < TM; i++) {
        int r = row0 + ty * TM + i;
        if (r < M) {
            float dv = g_dinv[r];
#pragma unroll
            for (int j = 0; j < TN; j++)
                hs[(size_t)r * BN + tx * TN + j] = __float2half_rn(acc[i][j] * dv);
        }
    }
}

// ---------------- pull aggregation over fp16 hs ----------------
__device__ __forceinline__ void acc8(float* f, uint4 u) {
    float2 p0 = __half22float2(*(__half2*)&u.x);
    float2 p1 = __half22float2(*((__half2*)&u.x + 1));
    float2 p2 = __half22float2(*(__half2*)&u.z);
    float2 p3 = __half22float2(*((__half2*)&u.z + 1));
    f[0] += p0.x; f[1] += p0.y; f[2] += p1.x; f[3] += p1.y;
    f[4] += p2.x; f[5] += p2.y; f[6] += p3.x; f[7] += p3.y;
}

template<int C>
__global__ void pull_k(const __half* __restrict__ hs, const float* __restrict__ bias,
                       __half* __restrict__ out, int n) {
    constexpr int CH8 = C / 8;
    int t = blockIdx.x * blockDim.x + threadIdx.x;
    int node = t / CH8;
    int c    = t % CH8;
    if (node >= n) return;

    const uint4* hs8 = (const uint4*)hs;
    float f[8] = {0, 0, 0, 0, 0, 0, 0, 0};
    acc8(f, hs8[(size_t)node * CH8 + c]);                  // self-loop
    const int beg = g_off[node];
    const int cnt = g_cnt[node];
    const int* __restrict__ cp = &g_csr[beg];

    int i = 0;
    for (; i + 4 <= cnt; i += 4) {
        int s0 = cp[i], s1 = cp[i + 1], s2 = cp[i + 2], s3 = cp[i + 3];
        uint4 u0 = hs8[(size_t)s0 * CH8 + c];
        uint4 u1 = hs8[(size_t)s1 * CH8 + c];
        uint4 u2 = hs8[(size_t)s2 * CH8 + c];
        uint4 u3 = hs8[(size_t)s3 * CH8 + c];
        acc8(f, u0); acc8(f, u1); acc8(f, u2); acc8(f, u3);
    }
    for (; i < cnt; i++) {
        int s = cp[i];
        acc8(f, hs8[(size_t)s * CH8 + c]);
    }

    float dv = g_dinv[node];
    float4 b0 = ((const float4*)bias)[c * 2];
    float4 b1 = ((const float4*)bias)[c * 2 + 1];
    float v0 = fmaxf(f[0] * dv + b0.x, 0.f), v1 = fmaxf(f[1] * dv + b0.y, 0.f);
    float v2 = fmaxf(f[2] * dv + b0.z, 0.f), v3 = fmaxf(f[3] * dv + b0.w, 0.f);
    float v4 = fmaxf(f[4] * dv + b1.x, 0.f), v5 = fmaxf(f[5] * dv + b1.y, 0.f);
    float v6 = fmaxf(f[6] * dv + b1.z, 0.f), v7 = fmaxf(f[7] * dv + b1.w, 0.f);
    uint4 u;
    *(__half2*)&u.x = __floats2half2_rn(v0, v1);
    *((__half2*)&u.x + 1) = __floats2half2_rn(v2, v3);
    *(__half2*)&u.z = __floats2half2_rn(v4, v5);
    *((__half2*)&u.z + 1) = __floats2half2_rn(v6, v7);
    ((uint4*)out)[(size_t)node * CH8 + c] = u;
}

// ------- fused pull3 + dinv + bias + log_softmax (warp per node) -----------
// hs: [n][40] fp16 (pre-scaled by dinv[src]); out: [n][40] fp32 log-softmax.
__global__ void pull_lsm_k(const __half* __restrict__ hs, const float* __restrict__ bias,
                           float* __restrict__ out, int n) {
    constexpr int CH8 = F3 / 8;               // 5 uint4 chunks per row
    int node = blockIdx.x * 8 + (threadIdx.x >> 5);
    int lane = threadIdx.x & 31;
    if (node >= n) return;

    const uint4* hs8 = (const uint4*)hs;
    float f[8] = {0, 0, 0, 0, 0, 0, 0, 0};
    if (lane < CH8) {
        acc8(f, hs8[(size_t)node * CH8 + lane]);           // self-loop
        const int beg = g_off[node];
        const int cnt = g_cnt[node];
        const int* __restrict__ cp = &g_csr[beg];
        int i = 0;
        for (; i + 4 <= cnt; i += 4) {
            int s0 = cp[i], s1 = cp[i + 1], s2 = cp[i + 2], s3 = cp[i + 3];
            uint4 u0 = hs8[(size_t)s0 * CH8 + lane];
            uint4 u1 = hs8[(size_t)s1 * CH8 + lane];
            uint4 u2 = hs8[(size_t)s2 * CH8 + lane];
            uint4 u3 = hs8[(size_t)s3 * CH8 + lane];
            acc8(f, u0); acc8(f, u1); acc8(f, u2); acc8(f, u3);
        }
        for (; i < cnt; i++) acc8(f, hs8[(size_t)cp[i] * CH8 + lane]);
    }

    float dv = g_dinv[node];
    float v[8];
    float m = -INFINITY;
    if (lane < CH8) {
#pragma unroll
        for (int j = 0; j < 8; j++) {
            v[j] = f[j] * dv + bias[lane * 8 + j];
            m = fmaxf(m, v[j]);
        }
    }
    // max over the 5 active lanes (lanes 5-7 hold -inf; reduction within 8-lane group)
#pragma unroll
    for (int o = 1; o < 8; o <<= 1) m = fmaxf(m, __shfl_xor_sync(0xffffffffu, m, o));
    float s = 0.f;
    if (lane < CH8) {
#pragma unroll
        for (int j = 0; j < 8; j++) s += expf(v[j] - m);
    }
#pragma unroll
    for (int o = 1; o < 8; o <<= 1) s += __shfl_xor_sync(0xffffffffu, s, o);
    float lse = logf(s) + m;

    if (lane < CH8) {
        float* op = out + (size_t)node * F3 + lane * 8;
        *(float4*)op       = make_float4(v[0] - lse, v[1] - lse, v[2] - lse, v[3] - lse);
        *(float4*)(op + 4) = make_float4(v[4] - lse, v[5] - lse, v[6] - lse, v[7] - lse);
    }
}

extern "C" void kernel_launch(void* const* d_in, const int* in_sizes, int n_in,
                              void* d_out, int out_size) {
    const float* x   = (const float*)d_in[0];
    const int*   ei  = (const int*)d_in[1];     // int32 (JAX x64 disabled)
    const float* W1  = (const float*)d_in[2];
    const float* b1  = (const float*)d_in[3];
    const float* W2  = (const float*)d_in[4];
    const float* b2  = (const float*)d_in[5];
    const float* W4  = (const float*)d_in[6];
    const float* b4  = (const float*)d_in[7];
    float* out = (float*)d_out;

    const int N = in_sizes[0] / F0;       // 100000
    const int E = in_sizes[1] / 2;        // 1600000
    const int* src = ei;
    const int* dst = ei + E;

    __half *H, *H2;
    int* CNT;
    cudaGetSymbolAddress((void**)&H,   g_h);
    cudaGetSymbolAddress((void**)&H2,  g_h2);
    cudaGetSymbolAddress((void**)&CNT, g_cnt);

    static cudaStream_t sM = nullptr, sS = nullptr;
    static cudaEvent_t  evF = nullptr, evS = nullptr, evJ = nullptr;
    if (!sM) {
        cudaStreamCreateWithFlags(&sM, cudaStreamNonBlocking);
        cudaStreamCreateWithFlags(&sS, cudaStreamNonBlocking);
        cudaEventCreateWithFlags(&evF, cudaEventDisableTiming);
        cudaEventCreateWithFlags(&evS, cudaEventDisableTiming);
        cudaEventCreateWithFlags(&evJ, cudaEventDisableTiming);
    }

    // ---- prologue on the capture stream: degree + dinv (GEMM1 needs dinv) ----
    cudaMemsetAsync(CNT, 0, (size_t)N * sizeof(int), 0);
    cnt_count_k<<<(E + 255) / 256, 256>>>(dst, E);
    dinv_k     <<<(N + 255) / 256, 256>>>(N);

    // ---- fork: CSR tail on sS concurrent with GEMM1 on sM ----
    cudaEventRecord(evF, 0);
    cudaStreamWaitEvent(sM, evF, 0);
    cudaStreamWaitEvent(sS, evF, 0);

    scan1_k   <<<NBLK, SCAN_B, 0, sS>>>(N);
    scan2_k   <<<1, SCAN_B, 0, sS>>>(NBLK);
    scan3_k   <<<(N + 255) / 256, 256, 0, sS>>>(N);
    csr_fill_k<<<(E + 255) / 256, 256, 0, sS>>>(src, dst, E);

    gemm_f16_k<128, float><<<(N + 127) / 128, 256, 0, sM>>>(x, W1, H, N, F0);

    // ---- join: pull1 needs CSR + GEMM1 ----
    cudaEventRecord(evS, sS);
    cudaStreamWaitEvent(sM, evS, 0);

    pull_k<128><<<((size_t)N * 16 + 255) / 256, 256, 0, sM>>>(H, b1, H2, N);

    gemm_f16_k<64, __half><<<(N + 127) / 128, 256, 0, sM>>>(H2, W2, H, N, F1);
    pull_k<64><<<((size_t)N * 8 + 255) / 256, 256, 0, sM>>>(H, b2, H2, N);

    gemm_scale_k<128, 40, 16, 8, 5><<<(N + 127) / 128, 128, 0, sM>>>(H2, W4, H, N, F2);
    pull_lsm_k<<<(N + 7) / 8, 256, 0, sM>>>(H, b4, out, N);

    // ---- join back to the capture stream ----
    cudaEventRecord(evJ, sM);
    cudaStreamWaitEvent(0, evJ, 0);
}

// round 15
// speedup vs baseline: 1.1551x; 1.1551x over previous
#include <cuda_runtime.h>
#include <cuda_fp16.h>
#include <math.h>

#define NN 100000
#define NE 1600000
#define F0 500
#define F1 128
#define F2 64
#define F3 40
#define SCAN_B 1024
#define NBLK ((NN + SCAN_B - 1) / SCAN_B)

// Static scratch (allocation-free rule: __device__ globals)
__device__ int   g_cnt [NN];
__device__ int   g_off [NN];
__device__ int   g_cur [NN];
__device__ int   g_bsum[SCAN_B];
__device__ int   g_csr [NE];
__device__ float g_dinv[NN];
__device__ __align__(16) __half g_h [(size_t)NN * F1];   // GEMM outputs (fp16, scaled)
__device__ __align__(16) __half g_h2[(size_t)NN * F1];   // pull outputs (fp16)

// ---------------- degree / CSR build ----------------
__global__ void cnt_count_k(const int* __restrict__ dst, int e) {
    int i = blockIdx.x * blockDim.x + threadIdx.x;
    if (i < e) atomicAdd(&g_cnt[dst[i]], 1);
}
__global__ void dinv_k(int n) {
    int i = blockIdx.x * blockDim.x + threadIdx.x;
    if (i < n) g_dinv[i] = rsqrtf((float)(g_cnt[i] + 1));
}
__global__ void scan1_k(int n) {
    __shared__ int sh[SCAN_B];
    int t = threadIdx.x, g = blockIdx.x * SCAN_B + t;
    int v = (g < n) ? g_cnt[g] : 0;
    sh[t] = v; __syncthreads();
#pragma unroll
    for (int o = 1; o < SCAN_B; o <<= 1) {
        int x = (t >= o) ? sh[t - o] : 0;
        __syncthreads();
        sh[t] += x;
        __syncthreads();
    }
    if (g < n) g_off[g] = sh[t] - v;
    if (t == SCAN_B - 1) g_bsum[blockIdx.x] = sh[t];
}
__global__ void scan2_k(int nb) {
    __shared__ int sh[SCAN_B];
    int t = threadIdx.x;
    int v = (t < nb) ? g_bsum[t] : 0;
    sh[t] = v; __syncthreads();
#pragma unroll
    for (int o = 1; o < SCAN_B; o <<= 1) {
        int x = (t >= o) ? sh[t - o] : 0;
        __syncthreads();
        sh[t] += x;
        __syncthreads();
    }
    if (t < nb) g_bsum[t] = sh[t] - v;
}
__global__ void scan3_k(int n) {
    int i = blockIdx.x * blockDim.x + threadIdx.x;
    if (i < n) {
        int o = g_off[i] + g_bsum[i / SCAN_B];
        g_off[i] = o;
        g_cur[i] = o;
    }
}
__global__ void csr_fill_k(const int* __restrict__ src, const int* __restrict__ dst, int e) {
    int i = blockIdx.x * blockDim.x + threadIdx.x;
    if (i < e) {
        int pos = atomicAdd(&g_cur[dst[i]], 1);
        g_csr[pos] = src[i];
    }
}

// ---------------- async-copy / mma helpers ----------------
template<typename T>
__device__ __forceinline__ void cp16(T* s, const T* g, bool pred) {
    unsigned sa = (unsigned)__cvta_generic_to_shared(s);
    int bytes = pred ? 16 : 0;
    asm volatile("cp.async.ca.shared.global [%0], [%1], 16, %2;"
                 :: "r"(sa), "l"(g), "r"(bytes));
}
#define CP_COMMIT() asm volatile("cp.async.commit_group;" ::: "memory")
#define CP_WAIT(N)  asm volatile("cp.async.wait_group %0;" :: "n"(N) : "memory")

__device__ __forceinline__ void mma_f16(float* d, const unsigned* a, const unsigned* b) {
    asm volatile(
        "mma.sync.aligned.m16n8k16.row.col.f32.f16.f16.f32 "
        "{%0,%1,%2,%3},{%4,%5,%6,%7},{%8,%9},{%0,%1,%2,%3};"
        : "+f"(d[0]), "+f"(d[1]), "+f"(d[2]), "+f"(d[3])
        : "r"(a[0]), "r"(a[1]), "r"(a[2]), "r"(a[3]), "r"(b[0]), "r"(b[1]));
}
__device__ __forceinline__ unsigned h2u(__half2 h) { return *(unsigned*)&h; }

// ---------------- fp16 MMA GEMM (proven R13 kernel, unchanged) ----------
template<int BN, typename TI>
__global__ void __launch_bounds__(256) gemm_f16_k(
        const TI* __restrict__ X, const float* __restrict__ W,
        __half* __restrict__ hs, int M, int Kreal) {
    constexpr int BM = 128, BK = 32;
    constexpr int XSTR = 40;
    constexpr int WSTR = 34;
    constexpr int NJ = BN / 16;
    constexpr int WITER = (BK / 2) * BN / 256;
    constexpr bool XF32 = (sizeof(TI) == 4);

    __shared__ __half Xs[2][BM][XSTR];
    __shared__ __half Wt[2][BN][WSTR];

    const int tid    = threadIdx.x;
    const int lane   = tid & 31;
    const int wid    = tid >> 5;
    const int warp_m = wid & 3;
    const int warp_n = wid >> 2;
    const int row0   = blockIdx.x * BM;
    const int lq     = lane >> 2;
    const int lr     = lane & 3;

    float acc[2][NJ][4];
#pragma unroll
    for (int i = 0; i < 2; i++)
#pragma unroll
        for (int j = 0; j < NJ; j++)
#pragma unroll
            for (int t = 0; t < 4; t++) acc[i][j][t] = 0.f;

    const int nchunk = (Kreal + BK - 1) / BK;

    unsigned xr[2][4];
    auto ldxr = [&](int k0) {
#pragma unroll
        for (int it = 0; it < 2; it++) {
            int idx = tid + it * 256;
            int r = idx >> 2, kv = idx & 3;
            int gr = row0 + r; if (gr >= M) gr = M - 1;
            int gk = k0 + kv * 8;
            const float* p = (const float*)X + (size_t)gr * Kreal + gk;
            float4 v0 = (gk + 4 <= Kreal) ? *(const float4*)p
                                          : make_float4(0.f, 0.f, 0.f, 0.f);
            float4 v1 = (gk + 8 <= Kreal) ? *(const float4*)(p + 4)
                                          : make_float4(0.f, 0.f, 0.f, 0.f);
            xr[it][0] = h2u(__floats2half2_rn(v0.x, v0.y));
            xr[it][1] = h2u(__floats2half2_rn(v0.z, v0.w));
            xr[it][2] = h2u(__floats2half2_rn(v1.x, v1.y));
            xr[it][3] = h2u(__floats2half2_rn(v1.z, v1.w));
        }
    };
    auto stx = [&](int s) {
#pragma unroll
        for (int it = 0; it < 2; it++) {
            int idx = tid + it * 256;
            int r = idx >> 2, kv = idx & 3;
            *(uint4*)&Xs[s][r][kv * 8] =
                make_uint4(xr[it][0], xr[it][1], xr[it][2], xr[it][3]);
        }
    };
    auto cpx = [&](int s, int k0) {
#pragma unroll
        for (int it = 0; it < 2; it++) {
            int idx = tid + it * 256;
            int r = idx >> 2, kv = idx & 3;
            int gr = row0 + r; if (gr >= M) gr = M - 1;
            cp16(&Xs[s][r][kv * 8],
                 (const __half*)X + (size_t)gr * Kreal + k0 + kv * 8, true);
        }
    };

    float wr[WITER][2];
    auto ldw = [&](int k0) {
#pragma unroll
        for (int it = 0; it < WITER; it++) {
            int idx = tid + it * 256;
            int n   = idx % BN;
            int kp  = idx / BN;
            int gk  = k0 + 2 * kp;
            wr[it][0] = (gk     < Kreal) ? W[(size_t)gk * BN + n]       : 0.f;
            wr[it][1] = (gk + 1 < Kreal) ? W[(size_t)(gk + 1) * BN + n] : 0.f;
        }
    };
    auto stw = [&](int s) {
#pragma unroll
        for (int it = 0; it < WITER; it++) {
            int idx = tid + it * 256;
            int n   = idx % BN;
            int kp  = idx / BN;
            *(__half2*)&Wt[s][n][2 * kp] = __floats2half2_rn(wr[it][0], wr[it][1]);
        }
    };

    if (XF32) { ldxr(0); stx(0); if (nchunk > 1) ldxr(BK); }
    else      { cpx(0, 0); CP_COMMIT(); }
    ldw(0); stw(0);
    if (nchunk > 1) ldw(BK);

    for (int kc = 0; kc < nchunk; kc++) {
        const int s = kc & 1;
        if (XF32) {
            if (kc + 1 < nchunk) stx(s ^ 1);
            if (kc + 2 < nchunk) ldxr((kc + 2) * BK);
        } else {
            if (kc + 1 < nchunk) { cpx(s ^ 1, (kc + 1) * BK); CP_COMMIT(); CP_WAIT(1); }
            else                 { CP_WAIT(0); }
        }
        if (kc + 1 < nchunk) stw(s ^ 1);
        if (kc + 2 < nchunk) ldw((kc + 2) * BK);
        __syncthreads();

#pragma unroll
        for (int ks = 0; ks < 2; ks++) {
            const int kb = ks * 16;
            unsigned a[2][4], b[NJ][2];
#pragma unroll
            for (int i = 0; i < 2; i++) {
                int r = warp_m * 32 + i * 16;
                a[i][0] = *(const unsigned*)&Xs[s][r + lq    ][kb + lr * 2    ];
                a[i][1] = *(const unsigned*)&Xs[s][r + lq + 8][kb + lr * 2    ];
                a[i][2] = *(const unsigned*)&Xs[s][r + lq    ][kb + lr * 2 + 8];
                a[i][3] = *(const unsigned*)&Xs[s][r + lq + 8][kb + lr * 2 + 8];
            }
#pragma unroll
            for (int j = 0; j < NJ; j++) {
                int n = warp_n * (BN / 2) + j * 8 + lq;
                b[j][0] = *(const unsigned*)&Wt[s][n][kb + lr * 2    ];
                b[j][1] = *(const unsigned*)&Wt[s][n][kb + lr * 2 + 8];
            }
#pragma unroll
            for (int i = 0; i < 2; i++)
#pragma unroll
                for (int j = 0; j < NJ; j++) mma_f16(acc[i][j], a[i], b[j]);
        }
        __syncthreads();
    }

#pragma unroll
    for (int i = 0; i < 2; i++) {
        int r_lo = row0 + warp_m * 32 + i * 16 + lq;
        int r_hi = r_lo + 8;
        float dv_lo = (r_lo < M) ? g_dinv[r_lo] : 0.f;
        float dv_hi = (r_hi < M) ? g_dinv[r_hi] : 0.f;
#pragma unroll
        for (int j = 0; j < NJ; j++) {
            int c = warp_n * (BN / 2) + j * 8 + lr * 2;
            if (r_lo < M)
                *(__half2*)&hs[(size_t)r_lo * BN + c] =
                    __floats2half2_rn(acc[i][j][0] * dv_lo, acc[i][j][1] * dv_lo);
            if (r_hi < M)
                *(__half2*)&hs[(size_t)r_hi * BN + c] =
                    __floats2half2_rn(acc[i][j][2] * dv_hi, acc[i][j][3] * dv_hi);
        }
    }
}

// ---------------- fp32 GEMM for 64->40, half in / half out ----------------
template<int BM, int BN, int BK, int TM, int TN>
__global__ void gemm_scale_k(const __half* __restrict__ X, const float* __restrict__ W,
                             __half* __restrict__ hs, int M, int K) {
    __shared__ float Xs[BM][BK + 1];
    __shared__ float Ws[BK][BN];
    constexpr int NT = (BM / TM) * (BN / TN);
    const int tid = threadIdx.x;
    const int tx  = tid % (BN / TN);
    const int ty  = tid / (BN / TN);
    const int row0 = blockIdx.x * BM;

    float acc[TM][TN];
#pragma unroll
    for (int i = 0; i < TM; i++)
#pragma unroll
        for (int j = 0; j < TN; j++) acc[i][j] = 0.f;

    for (int k0 = 0; k0 < K; k0 += BK) {
        for (int i = tid; i < BM * BK; i += NT) {
            int r = i / BK, kk = i % BK;
            int gr = row0 + r; if (gr >= M) gr = M - 1;
            int gk = k0 + kk;
            Xs[r][kk] = (gk < K) ? __half2float(X[(size_t)gr * K + gk]) : 0.f;
        }
        for (int i = tid; i < BK * BN; i += NT) {
            int kk = i / BN, c = i % BN;
            int gk = k0 + kk;
            Ws[kk][c] = (gk < K) ? W[(size_t)gk * BN + c] : 0.f;
        }
        __syncthreads();
#pragma unroll
        for (int kk = 0; kk < BK; kk++) {
            float a[TM], b[TN];
#pragma unroll
            for (int i = 0; i < TM; i++) a[i] = Xs[ty * TM + i][kk];
#pragma unroll
            for (int j = 0; j < TN; j++) b[j] = Ws[kk][tx * TN + j];
#pragma unroll
            for (int i = 0; i < TM; i++)
#pragma unroll
                for (int j = 0; j < TN; j++) acc[i][j] += a[i] * b[j];
        }
        __syncthreads();
    }

#pragma unroll
    for (int i = 0; i < TM; i++) {
        int r = row0 + ty * TM + i;
        if (r < M) {
            float dv = g_dinv[r];
#pragma unroll
            for (int j = 0; j < TN; j++)
                hs[(size_t)r * BN + tx * TN + j] = __float2half_rn(acc[i][j] * dv);
        }
    }
}

// ---------------- pull aggregation over fp16 hs (R13 layout) ----------------
__device__ __forceinline__ void acc8(float* f, uint4 u) {
    float2 p0 = __half22float2(*(__half2*)&u.x);
    float2 p1 = __half22float2(*((__half2*)&u.x + 1));
    float2 p2 = __half22float2(*(__half2*)&u.z);
    float2 p3 = __half22float2(*((__half2*)&u.z + 1));
    f[0] += p0.x; f[1] += p0.y; f[2] += p1.x; f[3] += p1.y;
    f[4] += p2.x; f[5] += p2.y; f[6] += p3.x; f[7] += p3.y;
}

template<int C>
__global__ void pull_k(const __half* __restrict__ hs, const float* __restrict__ bias,
                       __half* __restrict__ out, int n) {
    constexpr int CH8 = C / 8;
    int t = blockIdx.x * blockDim.x + threadIdx.x;
    int node = t / CH8;
    int c    = t % CH8;
    if (node >= n) return;

    const uint4* hs8 = (const uint4*)hs;
    float f[8] = {0, 0, 0, 0, 0, 0, 0, 0};
    acc8(f, hs8[(size_t)node * CH8 + c]);                  // self-loop
    const int beg = g_off[node];
    const int cnt = g_cnt[node];
    const int* __restrict__ cp = &g_csr[beg];

    int i = 0;
    for (; i + 4 <= cnt; i += 4) {
        int s0 = cp[i], s1 = cp[i + 1], s2 = cp[i + 2], s3 = cp[i + 3];
        uint4 u0 = hs8[(size_t)s0 * CH8 + c];
        uint4 u1 = hs8[(size_t)s1 * CH8 + c];
        uint4 u2 = hs8[(size_t)s2 * CH8 + c];
        uint4 u3 = hs8[(size_t)s3 * CH8 + c];
        acc8(f, u0); acc8(f, u1); acc8(f, u2); acc8(f, u3);
    }
    for (; i < cnt; i++) {
        int s = cp[i];
        acc8(f, hs8[(size_t)s * CH8 + c]);
    }

    float dv = g_dinv[node];
    float4 b0 = ((const float4*)bias)[c * 2];
    float4 b1 = ((const float4*)bias)[c * 2 + 1];
    float v0 = fmaxf(f[0] * dv + b0.x, 0.f), v1 = fmaxf(f[1] * dv + b0.y, 0.f);
    float v2 = fmaxf(f[2] * dv + b0.z, 0.f), v3 = fmaxf(f[3] * dv + b0.w, 0.f);
    float v4 = fmaxf(f[4] * dv + b1.x, 0.f), v5 = fmaxf(f[5] * dv + b1.y, 0.f);
    float v6 = fmaxf(f[6] * dv + b1.z, 0.f), v7 = fmaxf(f[7] * dv + b1.w, 0.f);
    uint4 u;
    *(__half2*)&u.x = __floats2half2_rn(v0, v1);
    *((__half2*)&u.x + 1) = __floats2half2_rn(v2, v3);
    *(__half2*)&u.z = __floats2half2_rn(v4, v5);
    *((__half2*)&u.z + 1) = __floats2half2_rn(v6, v7);
    ((uint4*)out)[(size_t)node * CH8 + c] = u;
}

// ------- fused pull3 + dinv + bias + log_softmax (gather layout preserved) ---
// 160 threads/block = 32 nodes x 5 chunks; every lane gathers (same MLP as R13
// pull3). Softmax reduction over the node's 5 threads via smem.
__global__ void __launch_bounds__(160) pull_lsm_k(
        const __half* __restrict__ hs, const float* __restrict__ bias,
        float* __restrict__ out, int n) {
    constexpr int CH8 = F3 / 8;               // 5
    __shared__ float red[32][CH8];
    __shared__ float bc [32];

    int t    = threadIdx.x;
    int ln   = t / CH8;                        // node within block, 0..31
    int c    = t % CH8;                        // chunk, 0..4
    int node = blockIdx.x * 32 + ln;
    bool valid = (node < n);

    float f[8] = {0, 0, 0, 0, 0, 0, 0, 0};
    if (valid) {
        const uint4* hs8 = (const uint4*)hs;
        acc8(f, hs8[(size_t)node * CH8 + c]);              // self-loop
        const int beg = g_off[node];
        const int cnt = g_cnt[node];
        const int* __restrict__ cp = &g_csr[beg];
        int i = 0;
        for (; i + 4 <= cnt; i += 4) {
            int s0 = cp[i], s1 = cp[i + 1], s2 = cp[i + 2], s3 = cp[i + 3];
            uint4 u0 = hs8[(size_t)s0 * CH8 + c];
            uint4 u1 = hs8[(size_t)s1 * CH8 + c];
            uint4 u2 = hs8[(size_t)s2 * CH8 + c];
            uint4 u3 = hs8[(size_t)s3 * CH8 + c];
            acc8(f, u0); acc8(f, u1); acc8(f, u2); acc8(f, u3);
        }
        for (; i < cnt; i++) acc8(f, hs8[(size_t)cp[i] * CH8 + c]);
    }

    float dv = valid ? g_dinv[node] : 0.f;
    float v[8];
    float m8 = -INFINITY;
#pragma unroll
    for (int j = 0; j < 8; j++) {
        v[j] = f[j] * dv + bias[c * 8 + j];
        m8 = fmaxf(m8, v[j]);
    }

    red[ln][c] = m8;
    __syncthreads();
    if (c == 0) {
        float m = red[ln][0];
#pragma unroll
        for (int k = 1; k < CH8; k++) m = fmaxf(m, red[ln][k]);
        bc[ln] = m;
    }
    __syncthreads();
    float m = bc[ln];

    float s8 = 0.f;
#pragma unroll
    for (int j = 0; j < 8; j++) s8 += expf(v[j] - m);
    red[ln][c] = s8;
    __syncthreads();
    if (c == 0) {
        float s = red[ln][0];
#pragma unroll
        for (int k = 1; k < CH8; k++) s += red[ln][k];
        bc[ln] = s;
    }
    __syncthreads();
    float lse = logf(bc[ln]) + m;

    if (valid) {
        float* op = out + (size_t)node * F3 + c * 8;
        *(float4*)op       = make_float4(v[0] - lse, v[1] - lse, v[2] - lse, v[3] - lse);
        *(float4*)(op + 4) = make_float4(v[4] - lse, v[5] - lse, v[6] - lse, v[7] - lse);
    }
}

extern "C" void kernel_launch(void* const* d_in, const int* in_sizes, int n_in,
                              void* d_out, int out_size) {
    const float* x   = (const float*)d_in[0];
    const int*   ei  = (const int*)d_in[1];     // int32 (JAX x64 disabled)
    const float* W1  = (const float*)d_in[2];
    const float* b1  = (const float*)d_in[3];
    const float* W2  = (const float*)d_in[4];
    const float* b2  = (const float*)d_in[5];
    const float* W4  = (const float*)d_in[6];
    const float* b4  = (const float*)d_in[7];
    float* out = (float*)d_out;

    const int N = in_sizes[0] / F0;       // 100000
    const int E = in_sizes[1] / 2;        // 1600000
    const int* src = ei;
    const int* dst = ei + E;

    __half *H, *H2;
    int* CNT;
    cudaGetSymbolAddress((void**)&H,   g_h);
    cudaGetSymbolAddress((void**)&H2,  g_h2);
    cudaGetSymbolAddress((void**)&CNT, g_cnt);

    static cudaStream_t sM = nullptr, sS = nullptr;
    static cudaEvent_t  evF = nullptr, evS = nullptr, evJ = nullptr;
    if (!sM) {
        cudaStreamCreateWithFlags(&sM, cudaStreamNonBlocking);
        cudaStreamCreateWithFlags(&sS, cudaStreamNonBlocking);
        cudaEventCreateWithFlags(&evF, cudaEventDisableTiming);
        cudaEventCreateWithFlags(&evS, cudaEventDisableTiming);
        cudaEventCreateWithFlags(&evJ, cudaEventDisableTiming);
    }

    // ---- prologue on the capture stream: degree + dinv (GEMM1 needs dinv) ----
    cudaMemsetAsync(CNT, 0, (size_t)N * sizeof(int), 0);
    cnt_count_k<<<(E + 255) / 256, 256>>>(dst, E);
    dinv_k     <<<(N + 255) / 256, 256>>>(N);

    // ---- fork: CSR tail on sS concurrent with GEMM1 on sM ----
    cudaEventRecord(evF, 0);
    cudaStreamWaitEvent(sM, evF, 0);
    cudaStreamWaitEvent(sS, evF, 0);

    scan1_k   <<<NBLK, SCAN_B, 0, sS>>>(N);
    scan2_k   <<<1, SCAN_B, 0, sS>>>(NBLK);
    scan3_k   <<<(N + 255) / 256, 256, 0, sS>>>(N);
    csr_fill_k<<<(E + 255) / 256, 256, 0, sS>>>(src, dst, E);

    gemm_f16_k<128, float><<<(N + 127) / 128, 256, 0, sM>>>(x, W1, H, N, F0);

    // ---- join: pull1 needs CSR + GEMM1 ----
    cudaEventRecord(evS, sS);
    cudaStreamWaitEvent(sM, evS, 0);

    pull_k<128><<<((size_t)N * 16 + 255) / 256, 256, 0, sM>>>(H, b1, H2, N);

    gemm_f16_k<64, __half><<<(N + 127) / 128, 256, 0, sM>>>(H2, W2, H, N, F1);
    pull_k<64><<<((size_t)N * 8 + 255) / 256, 256, 0, sM>>>(H, b2, H2, N);

    gemm_scale_k<128, 40, 16, 8, 5><<<(N + 127) / 128, 128, 0, sM>>>(H2, W4, H, N, F2);
    pull_lsm_k<<<(N + 31) / 32, 160, 0, sM>>>(H, b4, out, N);

    // ---- join back to the capture stream ----
    cudaEventRecord(evJ, sM);
    cudaStreamWaitEvent(0, evJ, 0);
}